// round 7
// baseline (speedup 1.0000x reference)
#include <cuda_runtime.h>
#include <cstdint>
#include <cstddef>

#define NMAX 50000
#define EMAX 600000
#define D 128
#define BM 128
#define BN 128
#define BK 16

// Scratch (no allocations allowed -> __device__ globals).
__device__ __align__(16) float g_dinv[NMAX];
__device__ __align__(16) float g_g1[NMAX * D];     // h1 = x@W1 (raw)
__device__ __align__(16) float g_agg1[NMAX * D];   // sum dinv[src]*h1[src] (incl self)
__device__ __align__(16) float g_x1[NMAX * D];     // relu(dinv*agg1 + b1)
__device__ __align__(16) float g_g2[NMAX * D];     // h2 = x1@W2 (raw)
__device__ __align__(16) float g_agg2[NMAX * D];

// CSR (by destination)
__device__ int g_cnt[NMAX];
__device__ int g_wr[NMAX];
__device__ int g_rowptr[NMAX + 1];
__device__ int g_srcidx[EMAX];

// ---------------------------------------------------------------------------
// CSR build.  edge_index is INT32.
// ---------------------------------------------------------------------------
__global__ void cnt_zero_kernel(int n) {
    int i = blockIdx.x * blockDim.x + threadIdx.x;
    if (i < n) g_cnt[i] = 0;
}

__global__ void hist_kernel(const int* __restrict__ ei, int E, int n) {
    int e = blockIdx.x * blockDim.x + threadIdx.x;
    if (e < E) {
        int c = ei[E + e];
        if ((unsigned)c < (unsigned)n) atomicAdd(&g_cnt[c], 1);
    }
}

__global__ __launch_bounds__(1024) void scan_kernel(int n) {
    __shared__ int s[1024];
    const int t = threadIdx.x;
    const int C = (n + 1023) / 1024;
    const int start = t * C;
    const int end = min(start + C, n);

    int sum = 0;
    for (int i = start; i < end; i++) sum += g_cnt[i];
    s[t] = sum;
    __syncthreads();
    for (int off = 1; off < 1024; off <<= 1) {
        int v = s[t];
        int o = (t >= off) ? s[t - off] : 0;
        __syncthreads();
        s[t] = v + o;
        __syncthreads();
    }
    int run = s[t] - sum;
    for (int i = start; i < end; i++) {
        g_rowptr[i] = run;
        g_wr[i] = run;
        g_dinv[i] = rsqrtf((float)(g_cnt[i] + 1));
        run += g_cnt[i];
    }
    if (t == 0) g_rowptr[n] = s[1023];
}

__global__ void place_kernel(const int* __restrict__ ei, int E, int n) {
    int e = blockIdx.x * blockDim.x + threadIdx.x;
    if (e < E) {
        int c = ei[E + e];
        int r = ei[e];
        if ((unsigned)c < (unsigned)n && (unsigned)r < (unsigned)n) {
            int p = atomicAdd(&g_wr[c], 1);
            g_srcidx[p] = r;
        }
    }
}

// ---------------------------------------------------------------------------
// Gather: one warp per node.  agg[c] = dinv[c]*h[c] + sum dinv[src]*h[src]
// (raw h buffers; dinv applied per source here, dinv[c] applied by consumer)
// ---------------------------------------------------------------------------
__global__ __launch_bounds__(256) void gather_kernel(int layer, int n)
{
    int node = (blockIdx.x * blockDim.x + threadIdx.x) >> 5;
    int lane = threadIdx.x & 31;
    if (node >= n) return;

    const float* __restrict__ h = (layer == 0) ? g_g1 : g_g2;
    float* __restrict__ agg = (layer == 0) ? g_agg1 : g_agg2;

    size_t base = (size_t)node * D + lane * 4;
    float dn = g_dinv[node];
    float4 sv = *(const float4*)(h + base);
    float4 acc = make_float4(sv.x * dn, sv.y * dn, sv.z * dn, sv.w * dn);

    int s = g_rowptr[node];
    int e = g_rowptr[node + 1];
    int i = s;
    for (; i + 4 <= e; i += 4) {
        int s0 = g_srcidx[i + 0], s1 = g_srcidx[i + 1];
        int s2 = g_srcidx[i + 2], s3 = g_srcidx[i + 3];
        float d0 = g_dinv[s0], d1 = g_dinv[s1], d2 = g_dinv[s2], d3 = g_dinv[s3];
        float4 v0 = *(const float4*)(h + (size_t)s0 * D + lane * 4);
        float4 v1 = *(const float4*)(h + (size_t)s1 * D + lane * 4);
        float4 v2 = *(const float4*)(h + (size_t)s2 * D + lane * 4);
        float4 v3 = *(const float4*)(h + (size_t)s3 * D + lane * 4);
        acc.x += v0.x * d0 + v1.x * d1 + v2.x * d2 + v3.x * d3;
        acc.y += v0.y * d0 + v1.y * d1 + v2.y * d2 + v3.y * d3;
        acc.z += v0.z * d0 + v1.z * d1 + v2.z * d2 + v3.z * d3;
        acc.w += v0.w * d0 + v1.w * d1 + v2.w * d2 + v3.w * d3;
    }
    for (; i < e; i++) {
        int src = g_srcidx[i];
        float ds = g_dinv[src];
        float4 v = *(const float4*)(h + (size_t)src * D + lane * 4);
        acc.x += v.x * ds; acc.y += v.y * ds; acc.z += v.z * ds; acc.w += v.w * ds;
    }
    *(float4*)(agg + base) = acc;
}

// ---------------------------------------------------------------------------
// GEMM: 256 threads, 128x128 tile, 8x8 register tile, K-chunk 16, A^T in smem.
// thread t: c0 = 4*(t&15) (cols c0..c0+3 and c0+64..c0+67), r0 = 8*(t>>4).
// ---------------------------------------------------------------------------

#define GEMM_MAINLOOP()                                                        \
    _Pragma("unroll 4")                                                        \
    for (int k = 0; k < BK; k++) {                                             \
        float4 a0 = *(const float4*)&sAT[k][r0];                               \
        float4 a1 = *(const float4*)&sAT[k][r0 + 4];                           \
        float4 w0 = *(const float4*)&sW[k][c0];                                \
        float4 w1 = *(const float4*)&sW[k][c0 + 64];                           \
        float av[8] = {a0.x, a0.y, a0.z, a0.w, a1.x, a1.y, a1.z, a1.w};        \
        float wv[8] = {w0.x, w0.y, w0.z, w0.w, w1.x, w1.y, w1.z, w1.w};        \
        _Pragma("unroll")                                                      \
        for (int ii = 0; ii < 8; ii++) {                                       \
            _Pragma("unroll")                                                  \
            for (int jj = 0; jj < 8; jj++)                                     \
                acc[ii][jj] = fmaf(av[ii], wv[jj], acc[ii][jj]);               \
        }                                                                      \
    }

// h1 = x @ W1 (raw)
__global__ __launch_bounds__(256) void gemm1_kernel(
    const float* __restrict__ A, const float* __restrict__ W, int n)
{
    __shared__ float sAT[BK][BM];
    __shared__ float sW[BK][BN];
    const int t = threadIdx.x;
    const int c0 = (t & 15) * 4;
    const int r0 = (t >> 4) * 8;
    const int m0 = blockIdx.x * BM;

    float acc[8][8];
#pragma unroll
    for (int i = 0; i < 8; i++)
#pragma unroll
        for (int j = 0; j < 8; j++) acc[i][j] = 0.0f;

    for (int k0 = 0; k0 < D; k0 += BK) {
        const float4* wsrc = (const float4*)(W + (size_t)k0 * D);
        ((float4*)sW)[t] = wsrc[t];
        ((float4*)sW)[t + 256] = wsrc[t + 256];
#pragma unroll
        for (int hh = 0; hh < 2; hh++) {
            int idx = t + hh * 256;
            int m = idx >> 2, kq = idx & 3;
            float4 v = make_float4(0.f, 0.f, 0.f, 0.f);
            if (m0 + m < n)
                v = *(const float4*)(A + (size_t)(m0 + m) * D + k0 + kq * 4);
            sAT[kq * 4 + 0][m] = v.x; sAT[kq * 4 + 1][m] = v.y;
            sAT[kq * 4 + 2][m] = v.z; sAT[kq * 4 + 3][m] = v.w;
        }
        __syncthreads();
        GEMM_MAINLOOP()
        __syncthreads();
    }

#pragma unroll
    for (int i = 0; i < 8; i++) {
        int m = m0 + r0 + i;
        if (m < n) {
            *(float4*)(g_g1 + (size_t)m * D + c0) =
                make_float4(acc[i][0], acc[i][1], acc[i][2], acc[i][3]);
            *(float4*)(g_g1 + (size_t)m * D + c0 + 64) =
                make_float4(acc[i][4], acc[i][5], acc[i][6], acc[i][7]);
        }
    }
}

// x1 = relu(dinv*agg1 + b1) on A-load (saved to g_x1); h2 = x1 @ W2 (raw)
__global__ __launch_bounds__(256) void gemm2_kernel(
    const float* __restrict__ W, const float* __restrict__ b1, int n)
{
    __shared__ float sAT[BK][BM];
    __shared__ float sW[BK][BN];
    const int t = threadIdx.x;
    const int c0 = (t & 15) * 4;
    const int r0 = (t >> 4) * 8;
    const int m0 = blockIdx.x * BM;

    float acc[8][8];
#pragma unroll
    for (int i = 0; i < 8; i++)
#pragma unroll
        for (int j = 0; j < 8; j++) acc[i][j] = 0.0f;

    for (int k0 = 0; k0 < D; k0 += BK) {
        const float4* wsrc = (const float4*)(W + (size_t)k0 * D);
        ((float4*)sW)[t] = wsrc[t];
        ((float4*)sW)[t + 256] = wsrc[t + 256];
#pragma unroll
        for (int hh = 0; hh < 2; hh++) {
            int idx = t + hh * 256;
            int m = idx >> 2, kq = idx & 3;
            float4 v = make_float4(0.f, 0.f, 0.f, 0.f);
            if (m0 + m < n) {
                float4 raw = *(const float4*)(g_agg1 + (size_t)(m0 + m) * D + k0 + kq * 4);
                float4 bb = *(const float4*)(b1 + k0 + kq * 4);
                float dm = g_dinv[m0 + m];
                v.x = fmaxf(fmaf(dm, raw.x, bb.x), 0.f);
                v.y = fmaxf(fmaf(dm, raw.y, bb.y), 0.f);
                v.z = fmaxf(fmaf(dm, raw.z, bb.z), 0.f);
                v.w = fmaxf(fmaf(dm, raw.w, bb.w), 0.f);
                *(float4*)(g_x1 + (size_t)(m0 + m) * D + k0 + kq * 4) = v;
            }
            sAT[kq * 4 + 0][m] = v.x; sAT[kq * 4 + 1][m] = v.y;
            sAT[kq * 4 + 2][m] = v.z; sAT[kq * 4 + 3][m] = v.w;
        }
        __syncthreads();
        GEMM_MAINLOOP()
        __syncthreads();
    }

#pragma unroll
    for (int i = 0; i < 8; i++) {
        int m = m0 + r0 + i;
        if (m < n) {
            *(float4*)(g_g2 + (size_t)m * D + c0) =
                make_float4(acc[i][0], acc[i][1], acc[i][2], acc[i][3]);
            *(float4*)(g_g2 + (size_t)m * D + c0 + 64) =
                make_float4(acc[i][4], acc[i][5], acc[i][6], acc[i][7]);
        }
    }
}

// out = [x1 | relu(dinv*agg2 + b2)] @ Wl + bl   (K = 256)
__global__ __launch_bounds__(256) void gemm3_kernel(
    const float* __restrict__ Wl, const float* __restrict__ b2,
    const float* __restrict__ bl, float* __restrict__ out, int n)
{
    __shared__ float sAT[BK][BM];
    __shared__ float sW[BK][BN];
    const int t = threadIdx.x;
    const int c0 = (t & 15) * 4;
    const int r0 = (t >> 4) * 8;
    const int m0 = blockIdx.x * BM;

    float acc[8][8];
#pragma unroll
    for (int i = 0; i < 8; i++)
#pragma unroll
        for (int j = 0; j < 8; j++) acc[i][j] = 0.0f;

    for (int k0 = 0; k0 < 2 * D; k0 += BK) {
        const float4* wsrc = (const float4*)(Wl + (size_t)k0 * D);
        ((float4*)sW)[t] = wsrc[t];
        ((float4*)sW)[t + 256] = wsrc[t + 256];
#pragma unroll
        for (int hh = 0; hh < 2; hh++) {
            int idx = t + hh * 256;
            int m = idx >> 2, kq = idx & 3;
            float4 v = make_float4(0.f, 0.f, 0.f, 0.f);
            if (m0 + m < n) {
                if (k0 < D) {
                    v = *(const float4*)(g_x1 + (size_t)(m0 + m) * D + k0 + kq * 4);
                } else {
                    int k2 = k0 - D + kq * 4;
                    float4 raw = *(const float4*)(g_agg2 + (size_t)(m0 + m) * D + k2);
                    float4 bb = *(const float4*)(b2 + k2);
                    float dm = g_dinv[m0 + m];
                    v.x = fmaxf(fmaf(dm, raw.x, bb.x), 0.f);
                    v.y = fmaxf(fmaf(dm, raw.y, bb.y), 0.f);
                    v.z = fmaxf(fmaf(dm, raw.z, bb.z), 0.f);
                    v.w = fmaxf(fmaf(dm, raw.w, bb.w), 0.f);
                }
            }
            sAT[kq * 4 + 0][m] = v.x; sAT[kq * 4 + 1][m] = v.y;
            sAT[kq * 4 + 2][m] = v.z; sAT[kq * 4 + 3][m] = v.w;
        }
        __syncthreads();
        GEMM_MAINLOOP()
        __syncthreads();
    }

    float4 bla = *(const float4*)(bl + c0);
    float4 blb = *(const float4*)(bl + c0 + 64);
#pragma unroll
    for (int i = 0; i < 8; i++) {
        int m = m0 + r0 + i;
        if (m < n) {
            *(float4*)(out + (size_t)m * D + c0) =
                make_float4(acc[i][0] + bla.x, acc[i][1] + bla.y,
                            acc[i][2] + bla.z, acc[i][3] + bla.w);
            *(float4*)(out + (size_t)m * D + c0 + 64) =
                make_float4(acc[i][4] + blb.x, acc[i][5] + blb.y,
                            acc[i][6] + blb.z, acc[i][7] + blb.w);
        }
    }
}

// ---------------------------------------------------------------------------
// Launch: single stream, no host state, graph-capture safe.
// ---------------------------------------------------------------------------
extern "C" void kernel_launch(void* const* d_in, const int* in_sizes, int n_in,
                              void* d_out, int out_size)
{
    const float* x  = (const float*)d_in[0];
    const int*   ei = (const int*)d_in[1];      // int32
    const float* W1 = (const float*)d_in[2];
    const float* b1 = (const float*)d_in[3];
    const float* W2 = (const float*)d_in[4];
    const float* b2 = (const float*)d_in[5];
    const float* Wl = (const float*)d_in[6];
    const float* bl = (const float*)d_in[7];
    float* out = (float*)d_out;

    const int n = in_sizes[0] / D;   // 50000
    const int E = in_sizes[1] / 2;   // 600000

    // CSR build (by destination) + dinv
    cnt_zero_kernel<<<(n + 255) / 256, 256>>>(n);
    hist_kernel<<<(E + 255) / 256, 256>>>(ei, E, n);
    scan_kernel<<<1, 1024>>>(n);
    place_kernel<<<(E + 255) / 256, 256>>>(ei, E, n);

    const int gblocks = (n + BM - 1) / BM;
    const int wblocks = (n + 7) / 8;

    gemm1_kernel<<<gblocks, 256>>>(x, W1, n);
    gather_kernel<<<wblocks, 256>>>(0, n);
    gemm2_kernel<<<gblocks, 256>>>(W2, b1, n);
    gather_kernel<<<wblocks, 256>>>(1, n);
    gemm3_kernel<<<gblocks, 256>>>(Wl, b2, bl, out, n);
}

// round 8
// speedup vs baseline: 1.1094x; 1.1094x over previous
#include <cuda_runtime.h>
#include <cstdint>
#include <cstddef>

#define NMAX 50000
#define EMAX 600000
#define D 128

// Scratch (no allocations allowed -> __device__ globals).
__device__ __align__(16) float g_dinv[NMAX];
__device__ __align__(16) float g_g1[NMAX * D];     // h1 = x@W1 (raw)
__device__ __align__(16) float g_agg1[NMAX * D];   // dinv-weighted gather of h1
__device__ __align__(16) float g_x1[NMAX * D];     // relu(dinv*agg1 + b1)
__device__ __align__(16) float g_g2[NMAX * D];     // h2 = x1@W2 (raw)
__device__ __align__(16) float g_agg2[NMAX * D];

// CSR (by destination)
__device__ int g_cnt[NMAX];
__device__ int g_wr[NMAX];
__device__ int g_rowptr[NMAX + 1];
__device__ int g_srcidx[EMAX];

// ---------------------------------------------------------------------------
// CSR build.  edge_index is INT32.
// ---------------------------------------------------------------------------
__global__ void cnt_zero_kernel(int n) {
    int i = blockIdx.x * blockDim.x + threadIdx.x;
    if (i < n) g_cnt[i] = 0;
}

__global__ void hist_kernel(const int* __restrict__ ei, int E, int n) {
    int e = blockIdx.x * blockDim.x + threadIdx.x;
    if (e < E) {
        int c = ei[E + e];
        if ((unsigned)c < (unsigned)n) atomicAdd(&g_cnt[c], 1);
    }
}

__global__ __launch_bounds__(1024) void scan_kernel(int n) {
    __shared__ int s[1024];
    const int t = threadIdx.x;
    const int C = (n + 1023) / 1024;
    const int start = t * C;
    const int end = min(start + C, n);

    int sum = 0;
    for (int i = start; i < end; i++) sum += g_cnt[i];
    s[t] = sum;
    __syncthreads();
    for (int off = 1; off < 1024; off <<= 1) {
        int v = s[t];
        int o = (t >= off) ? s[t - off] : 0;
        __syncthreads();
        s[t] = v + o;
        __syncthreads();
    }
    int run = s[t] - sum;
    for (int i = start; i < end; i++) {
        g_rowptr[i] = run;
        g_wr[i] = run;
        g_dinv[i] = rsqrtf((float)(g_cnt[i] + 1));
        run += g_cnt[i];
    }
    if (t == 0) g_rowptr[n] = s[1023];
}

__global__ void place_kernel(const int* __restrict__ ei, int E, int n) {
    int e = blockIdx.x * blockDim.x + threadIdx.x;
    if (e < E) {
        int c = ei[E + e];
        int r = ei[e];
        if ((unsigned)c < (unsigned)n && (unsigned)r < (unsigned)n) {
            int p = atomicAdd(&g_wr[c], 1);
            g_srcidx[p] = r;
        }
    }
}

// ---------------------------------------------------------------------------
// Gather: one warp per node.  agg[c] = dinv[c]*h[c] + sum dinv[src]*h[src]
// ---------------------------------------------------------------------------
__global__ __launch_bounds__(256) void gather_kernel(int layer, int n)
{
    int node = (blockIdx.x * blockDim.x + threadIdx.x) >> 5;
    int lane = threadIdx.x & 31;
    if (node >= n) return;

    const float* __restrict__ h = (layer == 0) ? g_g1 : g_g2;
    float* __restrict__ agg = (layer == 0) ? g_agg1 : g_agg2;

    size_t base = (size_t)node * D + lane * 4;
    float dn = g_dinv[node];
    float4 sv = *(const float4*)(h + base);
    float4 acc = make_float4(sv.x * dn, sv.y * dn, sv.z * dn, sv.w * dn);

    int s = g_rowptr[node];
    int e = g_rowptr[node + 1];
    int i = s;
    for (; i + 4 <= e; i += 4) {
        int s0 = g_srcidx[i + 0], s1 = g_srcidx[i + 1];
        int s2 = g_srcidx[i + 2], s3 = g_srcidx[i + 3];
        float d0 = g_dinv[s0], d1 = g_dinv[s1], d2 = g_dinv[s2], d3 = g_dinv[s3];
        float4 v0 = *(const float4*)(h + (size_t)s0 * D + lane * 4);
        float4 v1 = *(const float4*)(h + (size_t)s1 * D + lane * 4);
        float4 v2 = *(const float4*)(h + (size_t)s2 * D + lane * 4);
        float4 v3 = *(const float4*)(h + (size_t)s3 * D + lane * 4);
        acc.x += v0.x * d0 + v1.x * d1 + v2.x * d2 + v3.x * d3;
        acc.y += v0.y * d0 + v1.y * d1 + v2.y * d2 + v3.y * d3;
        acc.z += v0.z * d0 + v1.z * d1 + v2.z * d2 + v3.z * d3;
        acc.w += v0.w * d0 + v1.w * d1 + v2.w * d2 + v3.w * d3;
    }
    for (; i < e; i++) {
        int src = g_srcidx[i];
        float ds = g_dinv[src];
        float4 v = *(const float4*)(h + (size_t)src * D + lane * 4);
        acc.x += v.x * ds; acc.y += v.y * ds; acc.z += v.z * ds; acc.w += v.w * ds;
    }
    *(float4*)(agg + base) = acc;
}

// ---------------------------------------------------------------------------
// Tensor-core GEMM: mma.sync m16n8k8 tf32, 3-term hi/lo split (~fp32 accuracy)
// Block: 256 thr (8 warps), tile 128(M)x128(N). Warp tile 32x64:
//   warp w: m0w=(w&3)*32, n0w=(w>>2)*64.  K staged in 16-chunks, hi/lo in smem.
// MODE 0: A=x,  out=g_g1 (raw)
// MODE 1: A=relu(dinv*agg1+b1) (saved to g_x1), out=g_g2 (raw)
// MODE 2: A=[x1 | relu(dinv*agg2+b2)], K=256, out=out+bl
// ---------------------------------------------------------------------------
__device__ __forceinline__ float tf32r(float x) {
    uint32_t u;
    asm("cvt.rna.tf32.f32 %0, %1;" : "=r"(u) : "f"(x));
    return __uint_as_float(u);
}
__device__ __forceinline__ void mma8(float* c, const uint32_t* a,
                                     uint32_t b0, uint32_t b1) {
    asm("mma.sync.aligned.m16n8k8.row.col.f32.tf32.tf32.f32 "
        "{%0,%1,%2,%3}, {%4,%5,%6,%7}, {%8,%9}, {%0,%1,%2,%3};"
        : "+f"(c[0]), "+f"(c[1]), "+f"(c[2]), "+f"(c[3])
        : "r"(a[0]), "r"(a[1]), "r"(a[2]), "r"(a[3]), "r"(b0), "r"(b1));
}

template <int MODE>
__global__ __launch_bounds__(256) void gemm_tc(
    const float* __restrict__ A,          // MODE0: x
    const float* __restrict__ W,          // [K,128]
    const float* __restrict__ bias_stage, // MODE1: b1, MODE2: b2
    const float* __restrict__ bias_out,   // MODE2: bl
    float* __restrict__ outp,             // MODE2: out
    int n)
{
    constexpr int K = (MODE == 2) ? 256 : 128;
    __shared__ float sAh[16][132], sAl[16][132];  // A^T (k, m)
    __shared__ float sBh[16][132], sBl[16][132];  // W   (k, n)

    const int t = threadIdx.x;
    const int lane = t & 31, w = t >> 5;
    const int g = lane >> 2, q4 = lane & 3;
    const int m0w = (w & 3) * 32, n0w = (w >> 2) * 64;
    const int m0 = blockIdx.x * 128;

    float acc[2][8][4];
#pragma unroll
    for (int i = 0; i < 2; i++)
#pragma unroll
        for (int j = 0; j < 8; j++)
#pragma unroll
            for (int k = 0; k < 4; k++) acc[i][j][k] = 0.0f;

    for (int kc = 0; kc < K; kc += 16) {
        // ---- stage W chunk [16][128] as hi/lo (float4 rows -> STS.128) ----
#pragma unroll
        for (int i = 0; i < 2; i++) {
            int s = t + i * 256;               // 512 float4 slots
            int k = s >> 5, q = s & 31;
            float4 v = *(const float4*)(W + (size_t)(kc + k) * 128 + q * 4);
            float4 h, l;
            h.x = tf32r(v.x); l.x = tf32r(v.x - h.x);
            h.y = tf32r(v.y); l.y = tf32r(v.y - h.y);
            h.z = tf32r(v.z); l.z = tf32r(v.z - h.z);
            h.w = tf32r(v.w); l.w = tf32r(v.w - h.w);
            *(float4*)&sBh[k][q * 4] = h;
            *(float4*)&sBl[k][q * 4] = l;
        }
        // ---- stage A chunk [128][16] transposed to sA[k][m], hi/lo ----
#pragma unroll
        for (int i = 0; i < 2; i++) {
            int s = t + i * 256;               // 512 float4 slots
            int m = s >> 2, q = s & 3;         // cols kc+q*4 .. +3
            int gm = m0 + m;
            float4 v = make_float4(0.f, 0.f, 0.f, 0.f);
            if (gm < n) {
                if (MODE == 0) {
                    v = *(const float4*)(A + (size_t)gm * D + kc + q * 4);
                } else if (MODE == 1) {
                    float4 raw = *(const float4*)(g_agg1 + (size_t)gm * D + kc + q * 4);
                    float4 bb = *(const float4*)(bias_stage + kc + q * 4);
                    float dm = g_dinv[gm];
                    v.x = fmaxf(fmaf(dm, raw.x, bb.x), 0.f);
                    v.y = fmaxf(fmaf(dm, raw.y, bb.y), 0.f);
                    v.z = fmaxf(fmaf(dm, raw.z, bb.z), 0.f);
                    v.w = fmaxf(fmaf(dm, raw.w, bb.w), 0.f);
                    *(float4*)(g_x1 + (size_t)gm * D + kc + q * 4) = v;
                } else {
                    if (kc < 128) {
                        v = *(const float4*)(g_x1 + (size_t)gm * D + kc + q * 4);
                    } else {
                        int k2 = kc - 128 + q * 4;
                        float4 raw = *(const float4*)(g_agg2 + (size_t)gm * D + k2);
                        float4 bb = *(const float4*)(bias_stage + k2);
                        float dm = g_dinv[gm];
                        v.x = fmaxf(fmaf(dm, raw.x, bb.x), 0.f);
                        v.y = fmaxf(fmaf(dm, raw.y, bb.y), 0.f);
                        v.z = fmaxf(fmaf(dm, raw.z, bb.z), 0.f);
                        v.w = fmaxf(fmaf(dm, raw.w, bb.w), 0.f);
                    }
                }
            }
            float h0 = tf32r(v.x), h1 = tf32r(v.y), h2 = tf32r(v.z), h3 = tf32r(v.w);
            sAh[q * 4 + 0][m] = h0; sAl[q * 4 + 0][m] = tf32r(v.x - h0);
            sAh[q * 4 + 1][m] = h1; sAl[q * 4 + 1][m] = tf32r(v.y - h1);
            sAh[q * 4 + 2][m] = h2; sAl[q * 4 + 2][m] = tf32r(v.z - h2);
            sAh[q * 4 + 3][m] = h3; sAl[q * 4 + 3][m] = tf32r(v.w - h3);
        }
        __syncthreads();

        // ---- compute: 2 k-steps of 8 ----
#pragma unroll
        for (int kb = 0; kb < 16; kb += 8) {
            uint32_t ah[2][4], al[2][4];
#pragma unroll
            for (int ma = 0; ma < 2; ma++) {
                int mm = m0w + ma * 16 + g;
                ah[ma][0] = __float_as_uint(sAh[kb + q4][mm]);
                ah[ma][1] = __float_as_uint(sAh[kb + q4][mm + 8]);
                ah[ma][2] = __float_as_uint(sAh[kb + q4 + 4][mm]);
                ah[ma][3] = __float_as_uint(sAh[kb + q4 + 4][mm + 8]);
                al[ma][0] = __float_as_uint(sAl[kb + q4][mm]);
                al[ma][1] = __float_as_uint(sAl[kb + q4][mm + 8]);
                al[ma][2] = __float_as_uint(sAl[kb + q4 + 4][mm]);
                al[ma][3] = __float_as_uint(sAl[kb + q4 + 4][mm + 8]);
            }
#pragma unroll
            for (int na = 0; na < 8; na++) {
                int nn = n0w + na * 8 + g;
                uint32_t bh0 = __float_as_uint(sBh[kb + q4][nn]);
                uint32_t bh1 = __float_as_uint(sBh[kb + q4 + 4][nn]);
                uint32_t bl0 = __float_as_uint(sBl[kb + q4][nn]);
                uint32_t bl1 = __float_as_uint(sBl[kb + q4 + 4][nn]);
#pragma unroll
                for (int ma = 0; ma < 2; ma++) {
                    mma8(acc[ma][na], ah[ma], bh0, bh1);   // hi*hi
                    mma8(acc[ma][na], al[ma], bh0, bh1);   // lo*hi
                    mma8(acc[ma][na], ah[ma], bl0, bl1);   // hi*lo
                }
            }
        }
        __syncthreads();
    }

    // ---- epilogue ----
    float* dst = (MODE == 0) ? g_g1 : (MODE == 1) ? g_g2 : outp;
#pragma unroll
    for (int ma = 0; ma < 2; ma++) {
        int mlo = m0 + m0w + ma * 16 + g;
        int mhi = mlo + 8;
#pragma unroll
        for (int na = 0; na < 8; na++) {
            int nc = n0w + na * 8 + 2 * q4;
            float b0 = 0.f, b1 = 0.f;
            if (MODE == 2) { b0 = bias_out[nc]; b1 = bias_out[nc + 1]; }
            if (mlo < n) {
                float2 v = make_float2(acc[ma][na][0] + b0, acc[ma][na][1] + b1);
                *(float2*)(dst + (size_t)mlo * D + nc) = v;
            }
            if (mhi < n) {
                float2 v = make_float2(acc[ma][na][2] + b0, acc[ma][na][3] + b1);
                *(float2*)(dst + (size_t)mhi * D + nc) = v;
            }
        }
    }
}

// ---------------------------------------------------------------------------
// Launch: single stream, no host state, graph-capture safe.
// ---------------------------------------------------------------------------
extern "C" void kernel_launch(void* const* d_in, const int* in_sizes, int n_in,
                              void* d_out, int out_size)
{
    const float* x  = (const float*)d_in[0];
    const int*   ei = (const int*)d_in[1];      // int32
    const float* W1 = (const float*)d_in[2];
    const float* b1 = (const float*)d_in[3];
    const float* W2 = (const float*)d_in[4];
    const float* b2 = (const float*)d_in[5];
    const float* Wl = (const float*)d_in[6];
    const float* bl = (const float*)d_in[7];
    float* out = (float*)d_out;

    const int n = in_sizes[0] / D;   // 50000
    const int E = in_sizes[1] / 2;   // 600000

    // CSR build (by destination) + dinv
    cnt_zero_kernel<<<(n + 255) / 256, 256>>>(n);
    hist_kernel<<<(E + 255) / 256, 256>>>(ei, E, n);
    scan_kernel<<<1, 1024>>>(n);
    place_kernel<<<(E + 255) / 256, 256>>>(ei, E, n);

    const int gblocks = (n + 127) / 128;
    const int wblocks = (n + 7) / 8;

    gemm_tc<0><<<gblocks, 256>>>(x, W1, nullptr, nullptr, nullptr, n);
    gather_kernel<<<wblocks, 256>>>(0, n);
    gemm_tc<1><<<gblocks, 256>>>(nullptr, W2, b1, nullptr, nullptr, n);
    gather_kernel<<<wblocks, 256>>>(1, n);
    gemm_tc<2><<<gblocks, 256>>>(nullptr, Wl, b2, bl, out, n);
}

// round 11
// speedup vs baseline: 1.3293x; 1.1982x over previous
#include <cuda_runtime.h>
#include <cuda_bf16.h>
#include <cstdint>
#include <cstddef>

#define NMAX 50000
#define EMAX 600000
#define D 128

// ---------------------------------------------------------------------------
// Device scratch.  "p" buffers are packed bf16x2 planes: [row][k2] uint32,
// k2 = feature_pair index (2 consecutive features per uint32, low = even k).
// ---------------------------------------------------------------------------
__device__ __align__(16) float g_dinv[NMAX];
__device__ __align__(16) float g_g1[NMAX * D];   // h1 = x@W1 fp32
__device__ __align__(16) float g_g2[NMAX * D];   // h2 = x1@W2 fp32
__device__ __align__(16) uint32_t g_xph[NMAX * 64],  g_xpl[NMAX * 64];
__device__ __align__(16) uint32_t g_x1ph[NMAX * 64], g_x1pl[NMAX * 64];
__device__ __align__(16) uint32_t g_y2ph[NMAX * 64], g_y2pl[NMAX * 64];
// weights transposed: [n][k2]
__device__ __align__(16) uint32_t g_w1ph[128 * 64],  g_w1pl[128 * 64];
__device__ __align__(16) uint32_t g_w2ph[128 * 64],  g_w2pl[128 * 64];
__device__ __align__(16) uint32_t g_wlph[128 * 128], g_wlpl[128 * 128];
// CSR (by destination)
__device__ int g_cnt[NMAX];
__device__ int g_wr[NMAX];
__device__ int g_rowptr[NMAX + 1];
__device__ int g_srcidx[EMAX];

// bf16 split: pack 2 floats -> hi bf16x2 + lo bf16x2 (low 16 bits = first val)
__device__ __forceinline__ void split2(float a, float b, uint32_t& hi, uint32_t& lo) {
    __nv_bfloat16 ha = __float2bfloat16_rn(a), hb = __float2bfloat16_rn(b);
    float ra = a - __bfloat162float(ha), rb = b - __bfloat162float(hb);
    __nv_bfloat16 la = __float2bfloat16_rn(ra), lb = __float2bfloat16_rn(rb);
    hi = (uint32_t)__bfloat16_as_ushort(ha) | ((uint32_t)__bfloat16_as_ushort(hb) << 16);
    lo = (uint32_t)__bfloat16_as_ushort(la) | ((uint32_t)__bfloat16_as_ushort(lb) << 16);
}

// ---------------------------------------------------------------------------
// Prep: weights -> transposed packed hi/lo planes; x -> packed hi/lo planes
// ---------------------------------------------------------------------------
__global__ void prep_w_kernel(const float* __restrict__ W1,
                              const float* __restrict__ W2,
                              const float* __restrict__ Wl) {
    int idx = blockIdx.x * blockDim.x + threadIdx.x;
    if (idx < 8192) {                       // W1 [128][128] -> [n][64]
        int nn = idx & 127, k2 = idx >> 7;
        uint32_t h, l;
        split2(W1[(2 * k2) * 128 + nn], W1[(2 * k2 + 1) * 128 + nn], h, l);
        g_w1ph[nn * 64 + k2] = h; g_w1pl[nn * 64 + k2] = l;
    } else if (idx < 16384) {               // W2
        int r = idx - 8192;
        int nn = r & 127, k2 = r >> 7;
        uint32_t h, l;
        split2(W2[(2 * k2) * 128 + nn], W2[(2 * k2 + 1) * 128 + nn], h, l);
        g_w2ph[nn * 64 + k2] = h; g_w2pl[nn * 64 + k2] = l;
    } else if (idx < 32768) {               // Wl [256][128] -> [n][128]
        int r = idx - 16384;
        int nn = r & 127, k2 = r >> 7;      // k2 in 0..127
        uint32_t h, l;
        split2(Wl[(2 * k2) * 128 + nn], Wl[(2 * k2 + 1) * 128 + nn], h, l);
        g_wlph[nn * 128 + k2] = h; g_wlpl[nn * 128 + k2] = l;
    }
}

__global__ void convert_x_kernel(const float* __restrict__ x, int nf4) {
    int i = blockIdx.x * blockDim.x + threadIdx.x;
    if (i >= nf4) return;                   // nf4 = n*32 float4 chunks
    float4 v = ((const float4*)x)[i];
    uint2 h, l;
    split2(v.x, v.y, h.x, l.x);
    split2(v.z, v.w, h.y, l.y);
    ((uint2*)g_xph)[i] = h;
    ((uint2*)g_xpl)[i] = l;
}

// ---------------------------------------------------------------------------
// CSR build (edge_index is INT32)
// ---------------------------------------------------------------------------
__global__ void cnt_zero_kernel(int n) {
    int i = blockIdx.x * blockDim.x + threadIdx.x;
    if (i < n) g_cnt[i] = 0;
}
__global__ void hist_kernel(const int* __restrict__ ei, int E, int n) {
    int e = blockIdx.x * blockDim.x + threadIdx.x;
    if (e < E) {
        int c = ei[E + e];
        if ((unsigned)c < (unsigned)n) atomicAdd(&g_cnt[c], 1);
    }
}
__global__ __launch_bounds__(1024) void scan_kernel(int n) {
    __shared__ int s[1024];
    const int t = threadIdx.x;
    const int C = (n + 1023) / 1024;
    const int start = t * C, end = min(start + C, n);
    int sum = 0;
    for (int i = start; i < end; i++) sum += g_cnt[i];
    s[t] = sum;
    __syncthreads();
    for (int off = 1; off < 1024; off <<= 1) {
        int v = s[t];
        int o = (t >= off) ? s[t - off] : 0;
        __syncthreads();
        s[t] = v + o;
        __syncthreads();
    }
    int run = s[t] - sum;
    for (int i = start; i < end; i++) {
        g_rowptr[i] = run;
        g_wr[i] = run;
        g_dinv[i] = rsqrtf((float)(g_cnt[i] + 1));
        run += g_cnt[i];
    }
    if (t == 0) g_rowptr[n] = s[1023];
}
__global__ void place_kernel(const int* __restrict__ ei, int E, int n) {
    int e = blockIdx.x * blockDim.x + threadIdx.x;
    if (e < E) {
        int c = ei[E + e];
        int r = ei[e];
        if ((unsigned)c < (unsigned)n && (unsigned)r < (unsigned)n) {
            int p = atomicAdd(&g_wr[c], 1);
            g_srcidx[p] = r;
        }
    }
}

// ---------------------------------------------------------------------------
// Gather + fused relu/bias/dinv, emits packed bf16x2 hi/lo planes.
// layer 0: h=g_g1, bias=b1 -> x1 planes.  layer 1: h=g_g2, bias=b2 -> y2.
// ---------------------------------------------------------------------------
__global__ __launch_bounds__(256) void gather_kernel(int layer, int n,
                                                     const float* __restrict__ bias) {
    int node = (blockIdx.x * blockDim.x + threadIdx.x) >> 5;
    int lane = threadIdx.x & 31;
    if (node >= n) return;

    const float* __restrict__ h = (layer == 0) ? g_g1 : g_g2;
    uint32_t* __restrict__ oh = (layer == 0) ? g_x1ph : g_y2ph;
    uint32_t* __restrict__ ol = (layer == 0) ? g_x1pl : g_y2pl;

    size_t base = (size_t)node * D + lane * 4;
    float dn = g_dinv[node];
    float4 sv = *(const float4*)(h + base);
    float4 acc = make_float4(sv.x * dn, sv.y * dn, sv.z * dn, sv.w * dn);

    int s = g_rowptr[node], e = g_rowptr[node + 1];
    int i = s;
    for (; i + 4 <= e; i += 4) {
        int s0 = g_srcidx[i + 0], s1 = g_srcidx[i + 1];
        int s2 = g_srcidx[i + 2], s3 = g_srcidx[i + 3];
        float d0 = g_dinv[s0], d1 = g_dinv[s1], d2 = g_dinv[s2], d3 = g_dinv[s3];
        float4 v0 = *(const float4*)(h + (size_t)s0 * D + lane * 4);
        float4 v1 = *(const float4*)(h + (size_t)s1 * D + lane * 4);
        float4 v2 = *(const float4*)(h + (size_t)s2 * D + lane * 4);
        float4 v3 = *(const float4*)(h + (size_t)s3 * D + lane * 4);
        acc.x += v0.x * d0 + v1.x * d1 + v2.x * d2 + v3.x * d3;
        acc.y += v0.y * d0 + v1.y * d1 + v2.y * d2 + v3.y * d3;
        acc.z += v0.z * d0 + v1.z * d1 + v2.z * d2 + v3.z * d3;
        acc.w += v0.w * d0 + v1.w * d1 + v2.w * d2 + v3.w * d3;
    }
    for (; i < e; i++) {
        int src = g_srcidx[i];
        float ds = g_dinv[src];
        float4 v = *(const float4*)(h + (size_t)src * D + lane * 4);
        acc.x += v.x * ds; acc.y += v.y * ds; acc.z += v.z * ds; acc.w += v.w * ds;
    }
    float4 bb = *(const float4*)(bias + lane * 4);
    float r0 = fmaxf(fmaf(dn, acc.x, bb.x), 0.f);
    float r1 = fmaxf(fmaf(dn, acc.y, bb.y), 0.f);
    float r2 = fmaxf(fmaf(dn, acc.z, bb.z), 0.f);
    float r3 = fmaxf(fmaf(dn, acc.w, bb.w), 0.f);
    uint2 hh, ll;
    split2(r0, r1, hh.x, ll.x);
    split2(r2, r3, hh.y, ll.y);
    *(uint2*)(oh + (size_t)node * 64 + lane * 2) = hh;
    *(uint2*)(ol + (size_t)node * 64 + lane * 2) = ll;
}

// ---------------------------------------------------------------------------
// bf16 m16n8k16 tensor GEMM, 3-term hi/lo split.
// Block 256 thr (8 warps), tile 128(M)x128(N); warp w: m0w=(w&3)*32, n0w=(w>>2)*64.
// K staged in 32-feature chunks = 16 k2; smem sX[k2][row] packed uint32.
// Fragment map (k2 = packed pair index, g=lane>>2, q4=lane&3):
//   a0=sA[kb2+q4][mm]  a1=sA[kb2+q4][mm+8]  a2=sA[kb2+q4+4][mm]  a3=sA[kb2+q4+4][mm+8]
//   b0=sB[kb2+q4][nn]  b1=sB[kb2+q4+4][nn]
// MODE 0: A=x planes,  B=W1 -> g_g1.  MODE 1: A=x1, B=W2 -> g_g2.
// MODE 2: K2=128: A = x1 (k2<64) | y2 (k2>=64), B=Wl -> out+bl.
// ---------------------------------------------------------------------------
__device__ __forceinline__ void mma16(float* c, const uint32_t* a,
                                      uint32_t b0, uint32_t b1) {
    asm("mma.sync.aligned.m16n8k16.row.col.f32.bf16.bf16.f32 "
        "{%0,%1,%2,%3}, {%4,%5,%6,%7}, {%8,%9}, {%0,%1,%2,%3};"
        : "+f"(c[0]), "+f"(c[1]), "+f"(c[2]), "+f"(c[3])
        : "r"(a[0]), "r"(a[1]), "r"(a[2]), "r"(a[3]), "r"(b0), "r"(b1));
}

__device__ __forceinline__ void stage_plane(uint32_t (*dst)[132],
                                            const uint32_t* __restrict__ src,
                                            int m0, int nvalid, int strideK2, int k2off) {
    const int t = threadIdx.x;
#pragma unroll
    for (int i = 0; i < 2; i++) {
        int idx = t + i * 256;          // 512 uint4 = 128 rows x 16 k2
        int m = idx >> 2, q = idx & 3;
        uint4 v = make_uint4(0, 0, 0, 0);
        int gm = m0 + m;
        if (gm < nvalid)
            v = *(const uint4*)(src + (size_t)gm * strideK2 + k2off + q * 4);
        dst[q * 4 + 0][m] = v.x; dst[q * 4 + 1][m] = v.y;
        dst[q * 4 + 2][m] = v.z; dst[q * 4 + 3][m] = v.w;
    }
}

template <int MODE>
__global__ __launch_bounds__(256) void gemm_bf16(
    const float* __restrict__ bias_out,  // MODE2: bl
    float* __restrict__ outp,            // MODE2: out
    int n)
{
    constexpr int K2 = (MODE == 2) ? 128 : 64;
    __shared__ uint32_t sAh[16][132], sAl[16][132];
    __shared__ uint32_t sBh[16][132], sBl[16][132];

    const int t = threadIdx.x;
    const int lane = t & 31, w = t >> 5;
    const int g = lane >> 2, q4 = lane & 3;
    const int m0w = (w & 3) * 32, n0w = (w >> 2) * 64;
    const int m0 = blockIdx.x * 128;

    float acc[2][8][4];
#pragma unroll
    for (int i = 0; i < 2; i++)
#pragma unroll
        for (int j = 0; j < 8; j++)
#pragma unroll
            for (int k = 0; k < 4; k++) acc[i][j][k] = 0.0f;

    for (int kc2 = 0; kc2 < K2; kc2 += 16) {
        // ---- stage A hi/lo ----
        if (MODE == 0) {
            stage_plane(sAh, g_xph, m0, n, 64, kc2);
            stage_plane(sAl, g_xpl, m0, n, 64, kc2);
        } else if (MODE == 1) {
            stage_plane(sAh, g_x1ph, m0, n, 64, kc2);
            stage_plane(sAl, g_x1pl, m0, n, 64, kc2);
        } else {
            const uint32_t* ah = (kc2 < 64) ? g_x1ph : g_y2ph;
            const uint32_t* al = (kc2 < 64) ? g_x1pl : g_y2pl;
            int off = (kc2 < 64) ? kc2 : kc2 - 64;
            stage_plane(sAh, ah, m0, n, 64, off);
            stage_plane(sAl, al, m0, n, 64, off);
        }
        // ---- stage B hi/lo ----
        if (MODE == 0) {
            stage_plane(sBh, g_w1ph, 0, 128, 64, kc2);
            stage_plane(sBl, g_w1pl, 0, 128, 64, kc2);
        } else if (MODE == 1) {
            stage_plane(sBh, g_w2ph, 0, 128, 64, kc2);
            stage_plane(sBl, g_w2pl, 0, 128, 64, kc2);
        } else {
            stage_plane(sBh, g_wlph, 0, 128, 128, kc2);
            stage_plane(sBl, g_wlpl, 0, 128, 128, kc2);
        }
        __syncthreads();

#pragma unroll
        for (int kb2 = 0; kb2 < 16; kb2 += 8) {
            uint32_t ah[2][4], al[2][4];
#pragma unroll
            for (int ma = 0; ma < 2; ma++) {
                int mm = m0w + ma * 16 + g;
                ah[ma][0] = sAh[kb2 + q4][mm];
                ah[ma][1] = sAh[kb2 + q4][mm + 8];
                ah[ma][2] = sAh[kb2 + q4 + 4][mm];
                ah[ma][3] = sAh[kb2 + q4 + 4][mm + 8];
                al[ma][0] = sAl[kb2 + q4][mm];
                al[ma][1] = sAl[kb2 + q4][mm + 8];
                al[ma][2] = sAl[kb2 + q4 + 4][mm];
                al[ma][3] = sAl[kb2 + q4 + 4][mm + 8];
            }
#pragma unroll
            for (int na = 0; na < 8; na++) {
                int nn = n0w + na * 8 + g;
                uint32_t bh0 = sBh[kb2 + q4][nn];
                uint32_t bh1 = sBh[kb2 + q4 + 4][nn];
                uint32_t bl0 = sBl[kb2 + q4][nn];
                uint32_t bl1 = sBl[kb2 + q4 + 4][nn];
#pragma unroll
                for (int ma = 0; ma < 2; ma++) {
                    mma16(acc[ma][na], ah[ma], bh0, bh1);  // hi*hi
                    mma16(acc[ma][na], al[ma], bh0, bh1);  // lo*hi
                    mma16(acc[ma][na], ah[ma], bl0, bl1);  // hi*lo
                }
            }
        }
        __syncthreads();
    }

    // ---- epilogue: c0,c1 -> row mlo, cols nc,nc+1; c2,c3 -> row mlo+8 ----
    float* dst = (MODE == 0) ? g_g1 : (MODE == 1) ? g_g2 : outp;
#pragma unroll
    for (int ma = 0; ma < 2; ma++) {
        int mlo = m0 + m0w + ma * 16 + g;
        int mhi = mlo + 8;
#pragma unroll
        for (int na = 0; na < 8; na++) {
            int nc = n0w + na * 8 + 2 * q4;
            float b0 = 0.f, b1 = 0.f;
            if (MODE == 2) { b0 = bias_out[nc]; b1 = bias_out[nc + 1]; }
            if (mlo < n) {
                float2 v = make_float2(acc[ma][na][0] + b0, acc[ma][na][1] + b1);
                *(float2*)(dst + (size_t)mlo * D + nc) = v;
            }
            if (mhi < n) {
                float2 v = make_float2(acc[ma][na][2] + b0, acc[ma][na][3] + b1);
                *(float2*)(dst + (size_t)mhi * D + nc) = v;
            }
        }
    }
}

// ---------------------------------------------------------------------------
// Launch: single stream, no host state, graph-capture safe.
// ---------------------------------------------------------------------------
extern "C" void kernel_launch(void* const* d_in, const int* in_sizes, int n_in,
                              void* d_out, int out_size)
{
    const float* x  = (const float*)d_in[0];
    const int*   ei = (const int*)d_in[1];      // int32
    const float* W1 = (const float*)d_in[2];
    const float* b1 = (const float*)d_in[3];
    const float* W2 = (const float*)d_in[4];
    const float* b2 = (const float*)d_in[5];
    const float* Wl = (const float*)d_in[6];
    const float* bl = (const float*)d_in[7];
    float* out = (float*)d_out;

    const int n = in_sizes[0] / D;   // 50000
    const int E = in_sizes[1] / 2;   // 600000

    // conversions + CSR build
    prep_w_kernel<<<128, 256>>>(W1, W2, Wl);
    convert_x_kernel<<<(n * 32 + 255) / 256, 256>>>(x, n * 32);
    cnt_zero_kernel<<<(n + 255) / 256, 256>>>(n);
    hist_kernel<<<(E + 255) / 256, 256>>>(ei, E, n);
    scan_kernel<<<1, 1024>>>(n);
    place_kernel<<<(E + 255) / 256, 256>>>(ei, E, n);

    const int gblocks = (n + 127) / 128;
    const int wblocks = (n + 7) / 8;

    gemm_bf16<0><<<gblocks, 256>>>(nullptr, nullptr, n);
    gather_kernel<<<wblocks, 256>>>(0, n, b1);
    gemm_bf16<1><<<gblocks, 256>>>(nullptr, nullptr, n);
    gather_kernel<<<wblocks, 256>>>(1, n, b2);
    gemm_bf16<2><<<gblocks, 256>>>(bl, out, n);
}

// round 12
// speedup vs baseline: 1.3770x; 1.0359x over previous
#include <cuda_runtime.h>
#include <cuda_bf16.h>
#include <cstdint>
#include <cstddef>

#define NMAX 50000
#define EMAX 600000
#define D 128

// ---------------------------------------------------------------------------
// Device scratch.  "p" buffers are packed bf16x2 planes: [row][k2] uint32,
// k2 = feature_pair index (2 consecutive features per uint32, low = even k).
// ---------------------------------------------------------------------------
__device__ __align__(16) float g_dinv[NMAX];
__device__ __align__(16) float g_g1[NMAX * D];   // h1 = x@W1 fp32
__device__ __align__(16) float g_g2[NMAX * D];   // h2 = x1@W2 fp32
__device__ __align__(16) uint32_t g_x1ph[NMAX * 64], g_x1pl[NMAX * 64];
__device__ __align__(16) uint32_t g_y2ph[NMAX * 64], g_y2pl[NMAX * 64];
// weights transposed: [n][k2]
__device__ __align__(16) uint32_t g_w1ph[128 * 64],  g_w1pl[128 * 64];
__device__ __align__(16) uint32_t g_w2ph[128 * 64],  g_w2pl[128 * 64];
__device__ __align__(16) uint32_t g_wlph[128 * 128], g_wlpl[128 * 128];
// CSR (by destination)
__device__ int g_cnt[NMAX];
__device__ int g_wr[NMAX];
__device__ int g_rowptr[NMAX + 1];
__device__ int g_srcidx[EMAX];

// bf16 split: pack 2 floats -> hi bf16x2 + lo bf16x2 (low 16 bits = first val)
__device__ __forceinline__ void split2(float a, float b, uint32_t& hi, uint32_t& lo) {
    __nv_bfloat16 ha = __float2bfloat16_rn(a), hb = __float2bfloat16_rn(b);
    float ra = a - __bfloat162float(ha), rb = b - __bfloat162float(hb);
    __nv_bfloat16 la = __float2bfloat16_rn(ra), lb = __float2bfloat16_rn(rb);
    hi = (uint32_t)__bfloat16_as_ushort(ha) | ((uint32_t)__bfloat16_as_ushort(hb) << 16);
    lo = (uint32_t)__bfloat16_as_ushort(la) | ((uint32_t)__bfloat16_as_ushort(lb) << 16);
}

// ---------------------------------------------------------------------------
// Prep: weights -> transposed packed hi/lo planes; also zeroes g_cnt.
// grid covers max(n, 32768) threads.
// ---------------------------------------------------------------------------
__global__ void prep_kernel(const float* __restrict__ W1,
                            const float* __restrict__ W2,
                            const float* __restrict__ Wl, int n) {
    int idx = blockIdx.x * blockDim.x + threadIdx.x;
    if (idx < n) g_cnt[idx] = 0;
    if (idx < 8192) {                       // W1 [128][128] -> [n][64]
        int nn = idx & 127, k2 = idx >> 7;
        uint32_t h, l;
        split2(W1[(2 * k2) * 128 + nn], W1[(2 * k2 + 1) * 128 + nn], h, l);
        g_w1ph[nn * 64 + k2] = h; g_w1pl[nn * 64 + k2] = l;
    } else if (idx < 16384) {               // W2
        int r = idx - 8192;
        int nn = r & 127, k2 = r >> 7;
        uint32_t h, l;
        split2(W2[(2 * k2) * 128 + nn], W2[(2 * k2 + 1) * 128 + nn], h, l);
        g_w2ph[nn * 64 + k2] = h; g_w2pl[nn * 64 + k2] = l;
    } else if (idx < 32768) {               // Wl [256][128] -> [n][128]
        int r = idx - 16384;
        int nn = r & 127, k2 = r >> 7;      // k2 in 0..127
        uint32_t h, l;
        split2(Wl[(2 * k2) * 128 + nn], Wl[(2 * k2 + 1) * 128 + nn], h, l);
        g_wlph[nn * 128 + k2] = h; g_wlpl[nn * 128 + k2] = l;
    }
}

// ---------------------------------------------------------------------------
// CSR build (edge_index is INT32).  hist/place process 4 edges per thread.
// E is divisible by 4 here (600000); tail guard handles the general case.
// ---------------------------------------------------------------------------
__global__ void hist_kernel(const int* __restrict__ ei, int E, int n) {
    int e4 = blockIdx.x * blockDim.x + threadIdx.x;
    int e = e4 * 4;
    if (e + 4 <= E) {
        int4 c = *(const int4*)(ei + E + e);
        if ((unsigned)c.x < (unsigned)n) atomicAdd(&g_cnt[c.x], 1);
        if ((unsigned)c.y < (unsigned)n) atomicAdd(&g_cnt[c.y], 1);
        if ((unsigned)c.z < (unsigned)n) atomicAdd(&g_cnt[c.z], 1);
        if ((unsigned)c.w < (unsigned)n) atomicAdd(&g_cnt[c.w], 1);
    } else {
        for (; e < E; e++) {
            int c = ei[E + e];
            if ((unsigned)c < (unsigned)n) atomicAdd(&g_cnt[c], 1);
        }
    }
}

__global__ __launch_bounds__(1024) void scan_kernel(int n) {
    __shared__ int s[1024];
    const int t = threadIdx.x;
    const int C = (n + 1023) / 1024;
    const int start = t * C, end = min(start + C, n);
    int sum = 0;
    for (int i = start; i < end; i++) sum += g_cnt[i];
    s[t] = sum;
    __syncthreads();
    for (int off = 1; off < 1024; off <<= 1) {
        int v = s[t];
        int o = (t >= off) ? s[t - off] : 0;
        __syncthreads();
        s[t] = v + o;
        __syncthreads();
    }
    int run = s[t] - sum;
    for (int i = start; i < end; i++) {
        g_rowptr[i] = run;
        g_wr[i] = run;
        g_dinv[i] = rsqrtf((float)(g_cnt[i] + 1));
        run += g_cnt[i];
    }
    if (t == 0) g_rowptr[n] = s[1023];
}

__global__ void place_kernel(const int* __restrict__ ei, int E, int n) {
    int e4 = blockIdx.x * blockDim.x + threadIdx.x;
    int e = e4 * 4;
    if (e + 4 <= E) {
        int4 c = *(const int4*)(ei + E + e);
        int4 r = *(const int4*)(ei + e);
        if ((unsigned)c.x < (unsigned)n && (unsigned)r.x < (unsigned)n)
            g_srcidx[atomicAdd(&g_wr[c.x], 1)] = r.x;
        if ((unsigned)c.y < (unsigned)n && (unsigned)r.y < (unsigned)n)
            g_srcidx[atomicAdd(&g_wr[c.y], 1)] = r.y;
        if ((unsigned)c.z < (unsigned)n && (unsigned)r.z < (unsigned)n)
            g_srcidx[atomicAdd(&g_wr[c.z], 1)] = r.z;
        if ((unsigned)c.w < (unsigned)n && (unsigned)r.w < (unsigned)n)
            g_srcidx[atomicAdd(&g_wr[c.w], 1)] = r.w;
    } else {
        for (; e < E; e++) {
            int c = ei[E + e], r = ei[e];
            if ((unsigned)c < (unsigned)n && (unsigned)r < (unsigned)n)
                g_srcidx[atomicAdd(&g_wr[c], 1)] = r;
        }
    }
}

// ---------------------------------------------------------------------------
// Gather + fused relu/bias/dinv, emits packed bf16x2 hi/lo planes.
// One warp per node; 8-deep unrolled MLP.
// layer 0: h=g_g1, bias=b1 -> x1 planes.  layer 1: h=g_g2, bias=b2 -> y2.
// ---------------------------------------------------------------------------
__global__ __launch_bounds__(256) void gather_kernel(int layer, int n,
                                                     const float* __restrict__ bias) {
    int node = (blockIdx.x * blockDim.x + threadIdx.x) >> 5;
    int lane = threadIdx.x & 31;
    if (node >= n) return;

    const float* __restrict__ h = (layer == 0) ? g_g1 : g_g2;
    uint32_t* __restrict__ oh = (layer == 0) ? g_x1ph : g_y2ph;
    uint32_t* __restrict__ ol = (layer == 0) ? g_x1pl : g_y2pl;

    size_t base = (size_t)node * D + lane * 4;
    float dn = g_dinv[node];
    float4 sv = *(const float4*)(h + base);
    float4 acc = make_float4(sv.x * dn, sv.y * dn, sv.z * dn, sv.w * dn);

    int s = g_rowptr[node], e = g_rowptr[node + 1];
    int i = s;
    for (; i + 8 <= e; i += 8) {
        int si[8];
        float di[8];
        float4 vi[8];
#pragma unroll
        for (int j = 0; j < 8; j++) si[j] = g_srcidx[i + j];
#pragma unroll
        for (int j = 0; j < 8; j++) di[j] = g_dinv[si[j]];
#pragma unroll
        for (int j = 0; j < 8; j++)
            vi[j] = *(const float4*)(h + (size_t)si[j] * D + lane * 4);
#pragma unroll
        for (int j = 0; j < 8; j++) {
            acc.x += vi[j].x * di[j];
            acc.y += vi[j].y * di[j];
            acc.z += vi[j].z * di[j];
            acc.w += vi[j].w * di[j];
        }
    }
    for (; i + 4 <= e; i += 4) {
        int s0 = g_srcidx[i + 0], s1 = g_srcidx[i + 1];
        int s2 = g_srcidx[i + 2], s3 = g_srcidx[i + 3];
        float d0 = g_dinv[s0], d1 = g_dinv[s1], d2 = g_dinv[s2], d3 = g_dinv[s3];
        float4 v0 = *(const float4*)(h + (size_t)s0 * D + lane * 4);
        float4 v1 = *(const float4*)(h + (size_t)s1 * D + lane * 4);
        float4 v2 = *(const float4*)(h + (size_t)s2 * D + lane * 4);
        float4 v3 = *(const float4*)(h + (size_t)s3 * D + lane * 4);
        acc.x += v0.x * d0 + v1.x * d1 + v2.x * d2 + v3.x * d3;
        acc.y += v0.y * d0 + v1.y * d1 + v2.y * d2 + v3.y * d3;
        acc.z += v0.z * d0 + v1.z * d1 + v2.z * d2 + v3.z * d3;
        acc.w += v0.w * d0 + v1.w * d1 + v2.w * d2 + v3.w * d3;
    }
    for (; i < e; i++) {
        int src = g_srcidx[i];
        float ds = g_dinv[src];
        float4 v = *(const float4*)(h + (size_t)src * D + lane * 4);
        acc.x += v.x * ds; acc.y += v.y * ds; acc.z += v.z * ds; acc.w += v.w * ds;
    }
    float4 bb = *(const float4*)(bias + lane * 4);
    float r0 = fmaxf(fmaf(dn, acc.x, bb.x), 0.f);
    float r1 = fmaxf(fmaf(dn, acc.y, bb.y), 0.f);
    float r2 = fmaxf(fmaf(dn, acc.z, bb.z), 0.f);
    float r3 = fmaxf(fmaf(dn, acc.w, bb.w), 0.f);
    uint2 hh, ll;
    split2(r0, r1, hh.x, ll.x);
    split2(r2, r3, hh.y, ll.y);
    *(uint2*)(oh + (size_t)node * 64 + lane * 2) = hh;
    *(uint2*)(ol + (size_t)node * 64 + lane * 2) = ll;
}

// ---------------------------------------------------------------------------
// bf16 m16n8k16 tensor GEMM, 3-term hi/lo split.
// Block 256 thr (8 warps), tile 128(M)x128(N); warp w: m0w=(w&3)*32, n0w=(w>>2)*64.
// K staged in 32-feature chunks = 16 k2; smem sX[k2][row] packed uint32.
// Fragment map (k2 = packed pair index, g=lane>>2, q4=lane&3):
//   a0=sA[kb2+q4][mm]  a1=sA[kb2+q4][mm+8]  a2=sA[kb2+q4+4][mm]  a3=sA[kb2+q4+4][mm+8]
//   b0=sB[kb2+q4][nn]  b1=sB[kb2+q4+4][nn]
// MODE 0: A = fp32 x (split inline), B=W1 -> g_g1.
// MODE 1: A = x1 planes, B=W2 -> g_g2.
// MODE 2: K2=128: A = x1 (k2<64) | y2 (k2>=64), B=Wl -> out+bl.
// ---------------------------------------------------------------------------
__device__ __forceinline__ void mma16(float* c, const uint32_t* a,
                                      uint32_t b0, uint32_t b1) {
    asm("mma.sync.aligned.m16n8k16.row.col.f32.bf16.bf16.f32 "
        "{%0,%1,%2,%3}, {%4,%5,%6,%7}, {%8,%9}, {%0,%1,%2,%3};"
        : "+f"(c[0]), "+f"(c[1]), "+f"(c[2]), "+f"(c[3])
        : "r"(a[0]), "r"(a[1]), "r"(a[2]), "r"(a[3]), "r"(b0), "r"(b1));
}

__device__ __forceinline__ void stage_plane(uint32_t (*dst)[132],
                                            const uint32_t* __restrict__ src,
                                            int m0, int nvalid, int strideK2, int k2off) {
    const int t = threadIdx.x;
#pragma unroll
    for (int i = 0; i < 2; i++) {
        int idx = t + i * 256;          // 512 uint4 = 128 rows x 16 k2
        int m = idx >> 2, q = idx & 3;
        uint4 v = make_uint4(0, 0, 0, 0);
        int gm = m0 + m;
        if (gm < nvalid)
            v = *(const uint4*)(src + (size_t)gm * strideK2 + k2off + q * 4);
        dst[q * 4 + 0][m] = v.x; dst[q * 4 + 1][m] = v.y;
        dst[q * 4 + 2][m] = v.z; dst[q * 4 + 3][m] = v.w;
    }
}

// stage A from fp32 source with inline bf16 hi/lo split (MODE 0)
__device__ __forceinline__ void stage_split(uint32_t (*dh)[132], uint32_t (*dl)[132],
                                            const float* __restrict__ src,
                                            int m0, int nvalid, int kc2) {
    const int t = threadIdx.x;
#pragma unroll
    for (int i = 0; i < 4; i++) {
        int idx = t + i * 256;          // 1024 float4 = 128 rows x 8 float4
        int m = idx >> 3, q = idx & 7;  // q: float4 within chunk (2 k2 each)
        float4 v = make_float4(0.f, 0.f, 0.f, 0.f);
        int gm = m0 + m;
        if (gm < nvalid)
            v = *(const float4*)(src + (size_t)gm * D + kc2 * 2 + q * 4);
        uint32_t h0, l0, h1, l1;
        split2(v.x, v.y, h0, l0);
        split2(v.z, v.w, h1, l1);
        dh[2 * q + 0][m] = h0; dl[2 * q + 0][m] = l0;
        dh[2 * q + 1][m] = h1; dl[2 * q + 1][m] = l1;
    }
}

template <int MODE>
__global__ __launch_bounds__(256) void gemm_bf16(
    const float* __restrict__ Ax,        // MODE0: fp32 x
    const float* __restrict__ bias_out,  // MODE2: bl
    float* __restrict__ outp,            // MODE2: out
    int n)
{
    constexpr int K2 = (MODE == 2) ? 128 : 64;
    __shared__ uint32_t sAh[16][132], sAl[16][132];
    __shared__ uint32_t sBh[16][132], sBl[16][132];

    const int t = threadIdx.x;
    const int lane = t & 31, w = t >> 5;
    const int g = lane >> 2, q4 = lane & 3;
    const int m0w = (w & 3) * 32, n0w = (w >> 2) * 64;
    const int m0 = blockIdx.x * 128;

    float acc[2][8][4];
#pragma unroll
    for (int i = 0; i < 2; i++)
#pragma unroll
        for (int j = 0; j < 8; j++)
#pragma unroll
            for (int k = 0; k < 4; k++) acc[i][j][k] = 0.0f;

    for (int kc2 = 0; kc2 < K2; kc2 += 16) {
        // ---- stage A hi/lo ----
        if (MODE == 0) {
            stage_split(sAh, sAl, Ax, m0, n, kc2);
        } else if (MODE == 1) {
            stage_plane(sAh, g_x1ph, m0, n, 64, kc2);
            stage_plane(sAl, g_x1pl, m0, n, 64, kc2);
        } else {
            const uint32_t* ah = (kc2 < 64) ? g_x1ph : g_y2ph;
            const uint32_t* al = (kc2 < 64) ? g_x1pl : g_y2pl;
            int off = (kc2 < 64) ? kc2 : kc2 - 64;
            stage_plane(sAh, ah, m0, n, 64, off);
            stage_plane(sAl, al, m0, n, 64, off);
        }
        // ---- stage B hi/lo ----
        if (MODE == 0) {
            stage_plane(sBh, g_w1ph, 0, 128, 64, kc2);
            stage_plane(sBl, g_w1pl, 0, 128, 64, kc2);
        } else if (MODE == 1) {
            stage_plane(sBh, g_w2ph, 0, 128, 64, kc2);
            stage_plane(sBl, g_w2pl, 0, 128, 64, kc2);
        } else {
            stage_plane(sBh, g_wlph, 0, 128, 128, kc2);
            stage_plane(sBl, g_wlpl, 0, 128, 128, kc2);
        }
        __syncthreads();

#pragma unroll
        for (int kb2 = 0; kb2 < 16; kb2 += 8) {
            uint32_t ah[2][4], al[2][4];
#pragma unroll
            for (int ma = 0; ma < 2; ma++) {
                int mm = m0w + ma * 16 + g;
                ah[ma][0] = sAh[kb2 + q4][mm];
                ah[ma][1] = sAh[kb2 + q4][mm + 8];
                ah[ma][2] = sAh[kb2 + q4 + 4][mm];
                ah[ma][3] = sAh[kb2 + q4 + 4][mm + 8];
                al[ma][0] = sAl[kb2 + q4][mm];
                al[ma][1] = sAl[kb2 + q4][mm + 8];
                al[ma][2] = sAl[kb2 + q4 + 4][mm];
                al[ma][3] = sAl[kb2 + q4 + 4][mm + 8];
            }
#pragma unroll
            for (int na = 0; na < 8; na++) {
                int nn = n0w + na * 8 + g;
                uint32_t bh0 = sBh[kb2 + q4][nn];
                uint32_t bh1 = sBh[kb2 + q4 + 4][nn];
                uint32_t bl0 = sBl[kb2 + q4][nn];
                uint32_t bl1 = sBl[kb2 + q4 + 4][nn];
#pragma unroll
                for (int ma = 0; ma < 2; ma++) {
                    mma16(acc[ma][na], ah[ma], bh0, bh1);  // hi*hi
                    mma16(acc[ma][na], al[ma], bh0, bh1);  // lo*hi
                    mma16(acc[ma][na], ah[ma], bl0, bl1);  // hi*lo
                }
            }
        }
        __syncthreads();
    }

    // ---- epilogue: c0,c1 -> row mlo, cols nc,nc+1; c2,c3 -> row mlo+8 ----
    float* dst = (MODE == 0) ? g_g1 : (MODE == 1) ? g_g2 : outp;
#pragma unroll
    for (int ma = 0; ma < 2; ma++) {
        int mlo = m0 + m0w + ma * 16 + g;
        int mhi = mlo + 8;
#pragma unroll
        for (int na = 0; na < 8; na++) {
            int nc = n0w + na * 8 + 2 * q4;
            float b0 = 0.f, b1 = 0.f;
            if (MODE == 2) { b0 = bias_out[nc]; b1 = bias_out[nc + 1]; }
            if (mlo < n) {
                float2 v = make_float2(acc[ma][na][0] + b0, acc[ma][na][1] + b1);
                *(float2*)(dst + (size_t)mlo * D + nc) = v;
            }
            if (mhi < n) {
                float2 v = make_float2(acc[ma][na][2] + b0, acc[ma][na][3] + b1);
                *(float2*)(dst + (size_t)mhi * D + nc) = v;
            }
        }
    }
}

// ---------------------------------------------------------------------------
// Launch: single stream, no host state, graph-capture safe.  9 launches.
// ---------------------------------------------------------------------------
extern "C" void kernel_launch(void* const* d_in, const int* in_sizes, int n_in,
                              void* d_out, int out_size)
{
    const float* x  = (const float*)d_in[0];
    const int*   ei = (const int*)d_in[1];      // int32
    const float* W1 = (const float*)d_in[2];
    const float* b1 = (const float*)d_in[3];
    const float* W2 = (const float*)d_in[4];
    const float* b2 = (const float*)d_in[5];
    const float* Wl = (const float*)d_in[6];
    const float* bl = (const float*)d_in[7];
    float* out = (float*)d_out;

    const int n = in_sizes[0] / D;   // 50000
    const int E = in_sizes[1] / 2;   // 600000

    const int prep_threads = (n > 32768) ? n : 32768;
    prep_kernel<<<(prep_threads + 255) / 256, 256>>>(W1, W2, Wl, n);
    const int e4blocks = ((E + 3) / 4 + 255) / 256;
    hist_kernel<<<e4blocks, 256>>>(ei, E, n);
    scan_kernel<<<1, 1024>>>(n);
    place_kernel<<<e4blocks, 256>>>(ei, E, n);

    const int gblocks = (n + 127) / 128;
    const int wblocks = (n + 7) / 8;

    gemm_bf16<0><<<gblocks, 256>>>(x, nullptr, nullptr, n);
    gather_kernel<<<wblocks, 256>>>(0, n, b1);
    gemm_bf16<1><<<gblocks, 256>>>(nullptr, nullptr, nullptr, n);
    gather_kernel<<<wblocks, 256>>>(1, n, b2);
    gemm_bf16<2><<<gblocks, 256>>>(nullptr, bl, out, n);
}